// round 2
// baseline (speedup 1.0000x reference)
#include <cuda_runtime.h>
#include <math.h>

#define NN 10000
#define NE 160000
#define NG 64

// ------------------------------------------------------------------ scratch
__device__ __align__(128) float g_f[57200000];
__device__ double g_d[512];
__device__ int    g_i[200032];

// float offsets
#define O_EA    0UL
#define O_EB    20480000UL
#define O_H     40960000UL
#define O_X1    44800000UL
#define O_XB    46080000UL
#define O_XC    47360000UL
#define O_XO    48640000UL
#define O_AGGE  49920000UL
#define O_AGGHS 53760000UL
#define O_HM    55040000UL
#define O_LOG   56320000UL
#define O_EATTN 56800000UL
#define O_SSRC  56960000UL
#define O_SDST  56990000UL
#define O_ASUM  57020000UL
#define O_WPERM 57050000UL
#define O_A2    57099152UL
#define O_C2    57099536UL
#define O_WEM   57099540UL
#define O_B1M   57115924UL
#define O_MU    57116052UL
#define O_INV   57116180UL
#define O_MUC   57116308UL
#define O_INVC  57116436UL
#define O_MUO   57116564UL
#define O_INVO  57116692UL
#define O_GC    57116820UL
#define O_GO    57125012UL

// ------------------------------------------------------------------ CSR build
__global__ void k_count(const int* __restrict__ col, int* __restrict__ cnt) {
    int i = blockIdx.x * blockDim.x + threadIdx.x;
    if (i < NE) atomicAdd(&cnt[col[i]], 1);
}

__global__ void k_scan(const int* __restrict__ cnt, int* __restrict__ offs) {
    __shared__ int sm[1024];
    int t = threadIdx.x;
    const int per = (NN + 1023) / 1024;
    int b = t * per, e = min(NN, b + per);
    int s = 0;
    for (int i = b; i < e; i++) s += cnt[i];
    sm[t] = s;
    __syncthreads();
    for (int o = 1; o < 1024; o <<= 1) {
        int v = (t >= o) ? sm[t - o] : 0;
        __syncthreads();
        sm[t] += v;
        __syncthreads();
    }
    int base = (t == 0) ? 0 : sm[t - 1];
    for (int i = b; i < e; i++) { offs[i] = base; base += cnt[i]; }
    if (t == 1023) offs[NN] = sm[1023];
}

__global__ void k_fill(const int* __restrict__ col, int* __restrict__ fill,
                       int* __restrict__ perm) {
    int i = blockIdx.x * blockDim.x + threadIdx.x;
    if (i < NE) { int p = atomicAdd(&fill[col[i]], 1); perm[p] = i; }
}

// ------------------------------------------------------------------ BN (node features)
__global__ void k_colstat(const float* __restrict__ X, int rows, double* __restrict__ sums) {
    int c = threadIdx.x;  // 128
    double s = 0, s2 = 0;
    for (int r = blockIdx.x; r < rows; r += gridDim.x) {
        float v = X[(size_t)r * 128 + c];
        s += v; s2 += (double)v * v;
    }
    atomicAdd(&sums[c], s);
    atomicAdd(&sums[128 + c], s2);
}

__global__ void k_bnfin(const double* __restrict__ sums, int rows,
                        float* __restrict__ mu, float* __restrict__ inv) {
    int c = threadIdx.x;
    double m = sums[c] / rows;
    double v = sums[128 + c] / rows - m * m;
    mu[c] = (float)m;
    inv[c] = (float)rsqrt(v + 1e-5);
}

__global__ void k_bnapply(const float* __restrict__ X, const float* __restrict__ mu,
                          const float* __restrict__ inv, float* __restrict__ Y, int rows) {
    int i = blockIdx.x * blockDim.x + threadIdx.x;
    if (i < rows * 128) {
        int c = i & 127;
        Y[i] = (X[i] - mu[c]) * inv[c] + 1e-4f;
    }
}

// BN moments of edge_c = attn*e and edge_o = (1-attn)*e in one pass
__global__ void k_edgemom(const float* __restrict__ E4, const float* __restrict__ attn,
                          double* __restrict__ sums) {
    int t = threadIdx.x;  // 128
    double sc = 0, sc2 = 0, so = 0, so2 = 0;
    for (int r = blockIdx.x; r < NE; r += gridDim.x) {
        float w = attn[r];
        float v = E4[(size_t)r * 128 + t];
        float tc = w * v, to = (1.f - w) * v;
        sc += tc; sc2 += (double)tc * tc;
        so += to; so2 += (double)to * to;
    }
    atomicAdd(&sums[t], sc);
    atomicAdd(&sums[128 + t], sc2);
    atomicAdd(&sums[256 + t], so);
    atomicAdd(&sums[384 + t], so2);
}

__global__ void k_edgemomfin(const double* __restrict__ sums,
                             float* __restrict__ muc, float* __restrict__ invc,
                             float* __restrict__ muo, float* __restrict__ invo) {
    int c = threadIdx.x;
    double m = sums[c] / NE, v = sums[128 + c] / NE - m * m;
    muc[c] = (float)m; invc[c] = (float)rsqrt(v + 1e-5);
    m = sums[256 + c] / NE; v = sums[384 + c] / NE - m * m;
    muo[c] = (float)m; invo[c] = (float)rsqrt(v + 1e-5);
}

// ------------------------------------------------------------------ per-layer weight prep
// A2[f,h] = sum_d We[f,h,d]*a2[h,d]; C2[h] = sum_d b1[h,d]*a2[h,d]
// WeM[f,d] = mean_h We[f,h,d]; B1M[d] = mean_h b1[h,d]
// Wperm[(h*fe+f), d] = We[f,h,d]
__global__ void k_wprep(const float* __restrict__ We, const float* __restrict__ b1,
                        const float* __restrict__ a2, int fe, int need_em,
                        float* __restrict__ A2, float* __restrict__ C2,
                        float* __restrict__ WeM, float* __restrict__ B1M,
                        float* __restrict__ Wperm) {
    int i = blockIdx.x * blockDim.x + threadIdx.x;
    if (i < fe * 3) {
        int f = i / 3, h = i % 3;
        float s = 0;
        for (int d = 0; d < 128; d++) s += We[(size_t)(f * 3 + h) * 128 + d] * a2[h * 128 + d];
        A2[i] = s;
    }
    if (i < 3) {
        float s = 0;
        for (int d = 0; d < 128; d++) s += b1[i * 128 + d] * a2[i * 128 + d];
        C2[i] = s;
    }
    if (i < 128) B1M[i] = (b1[i] + b1[128 + i] + b1[256 + i]) * (1.f / 3.f);
    if (need_em && i < fe * 128) {
        int f = i / 128, d = i % 128;
        WeM[i] = (We[(size_t)(f * 3) * 128 + d] + We[(size_t)(f * 3 + 1) * 128 + d] +
                  We[(size_t)(f * 3 + 2) * 128 + d]) * (1.f / 3.f);
    }
    if (i < 3 * fe * 128) {
        int hi = i / 128, d = i % 128;
        int h = hi / fe, f = hi % fe;
        Wperm[i] = We[(size_t)(f * 3 + h) * 128 + d];
    }
}

// ------------------------------------------------------------------ node scores from H
__global__ void k_nodescore(const float* __restrict__ H, const float* __restrict__ a,
                            float* __restrict__ ssrc, float* __restrict__ sdst,
                            float* __restrict__ hm) {
    __shared__ float red[6][128];
    int n = blockIdx.x, t = threadIdx.x;
    float h0 = H[(size_t)n * 384 + t];
    float h1 = H[(size_t)n * 384 + 128 + t];
    float h2 = H[(size_t)n * 384 + 256 + t];
    hm[(size_t)n * 128 + t] = (h0 + h1 + h2) * (1.f / 3.f);
    red[0][t] = h0 * a[t];       red[1][t] = h1 * a[128 + t]; red[2][t] = h2 * a[256 + t];
    red[3][t] = h0 * a[384 + t]; red[4][t] = h1 * a[512 + t]; red[5][t] = h2 * a[640 + t];
    __syncthreads();
    for (int o = 64; o > 0; o >>= 1) {
        if (t < o) {
            #pragma unroll
            for (int q = 0; q < 6; q++) red[q][t] += red[q][t + o];
        }
        __syncthreads();
    }
    if (t < 3) {
        ssrc[n * 3 + t] = red[t][0];
        sdst[n * 3 + t] = red[3 + t][0];
    }
}

// ------------------------------------------------------------------ edge logits (warp/edge)
__global__ void k_edgelogit(const float* __restrict__ ef, int fe,
                            const int* __restrict__ row, const int* __restrict__ colv,
                            const float* __restrict__ ssrc, const float* __restrict__ sdst,
                            const float* __restrict__ A2, const float* __restrict__ C2,
                            const float* __restrict__ attn, int oneminus,
                            const float* __restrict__ mu, const float* __restrict__ inv,
                            float* __restrict__ logits, float* __restrict__ eattn, int do_attn) {
    int gw = (blockIdx.x * blockDim.x + threadIdx.x) >> 5;
    int lane = threadIdx.x & 31;
    if (gw >= NE) return;
    float w = 1.f;
    if (attn) { w = attn[gw]; if (oneminus) w = 1.f - w; }
    float p0 = 0, p1 = 0, p2 = 0;
    for (int i = lane; i < fe; i += 32) {
        float v = ef[(size_t)gw * fe + i];
        if (mu) v = (w * v - mu[i]) * inv[i] + 1e-4f;
        p0 += v * A2[i * 3 + 0];
        p1 += v * A2[i * 3 + 1];
        p2 += v * A2[i * 3 + 2];
    }
    #pragma unroll
    for (int o = 16; o > 0; o >>= 1) {
        p0 += __shfl_down_sync(0xffffffffu, p0, o);
        p1 += __shfl_down_sync(0xffffffffu, p1, o);
        p2 += __shfl_down_sync(0xffffffffu, p2, o);
    }
    if (lane == 0) {
        int r = row[gw], c = colv[gw];
        float l0 = ssrc[r * 3 + 0] + sdst[c * 3 + 0] + p0 + C2[0];
        float l1 = ssrc[r * 3 + 1] + sdst[c * 3 + 1] + p1 + C2[1];
        float l2 = ssrc[r * 3 + 2] + sdst[c * 3 + 2] + p2 + C2[2];
        l0 = l0 > 0.f ? l0 : 0.2f * l0;
        l1 = l1 > 0.f ? l1 : 0.2f * l1;
        l2 = l2 > 0.f ? l2 : 0.2f * l2;
        logits[gw * 3 + 0] = l0;
        logits[gw * 3 + 1] = l1;
        logits[gw * 3 + 2] = l2;
        if (do_attn) {
            float m = (l0 + l1 + l2) * (1.f / 3.f);
            eattn[gw] = 1.f / (1.f + expf(-m));
        }
    }
}

// ------------------------------------------------------------------ per-node softmax + aggregation
__global__ void k_nodeagg(const int* __restrict__ offs, const int* __restrict__ perm,
                          const int* __restrict__ row,
                          const float* __restrict__ logits, const float* __restrict__ H,
                          const float* __restrict__ ef, int fe,
                          const float* __restrict__ attn, int oneminus,
                          const float* __restrict__ mu, const float* __restrict__ inv,
                          float* __restrict__ agghs, float* __restrict__ aggE,
                          float* __restrict__ asum) {
    __shared__ float red[3][128];
    __shared__ float smax[3], ssum[3];
    int n = blockIdx.x, t = threadIdx.x;
    int s = offs[n], e = offs[n + 1];

    // pass 1: per-head max
    float mx0 = -1e30f, mx1 = -1e30f, mx2 = -1e30f;
    for (int j = s + t; j < e; j += 128) {
        int id = perm[j];
        mx0 = fmaxf(mx0, logits[id * 3 + 0]);
        mx1 = fmaxf(mx1, logits[id * 3 + 1]);
        mx2 = fmaxf(mx2, logits[id * 3 + 2]);
    }
    red[0][t] = mx0; red[1][t] = mx1; red[2][t] = mx2;
    __syncthreads();
    for (int o = 64; o > 0; o >>= 1) {
        if (t < o) {
            red[0][t] = fmaxf(red[0][t], red[0][t + o]);
            red[1][t] = fmaxf(red[1][t], red[1][t + o]);
            red[2][t] = fmaxf(red[2][t], red[2][t + o]);
        }
        __syncthreads();
    }
    if (t < 3) smax[t] = red[t][0];
    __syncthreads();
    float m0 = smax[0], m1 = smax[1], m2 = smax[2];

    // pass 2: per-head exp-sums
    float sm0 = 0, sm1 = 0, sm2 = 0;
    for (int j = s + t; j < e; j += 128) {
        int id = perm[j];
        sm0 += expf(logits[id * 3 + 0] - m0);
        sm1 += expf(logits[id * 3 + 1] - m1);
        sm2 += expf(logits[id * 3 + 2] - m2);
    }
    red[0][t] = sm0; red[1][t] = sm1; red[2][t] = sm2;
    __syncthreads();
    for (int o = 64; o > 0; o >>= 1) {
        if (t < o) {
            red[0][t] += red[0][t + o];
            red[1][t] += red[1][t + o];
            red[2][t] += red[2][t + o];
        }
        __syncthreads();
    }
    if (t < 3) ssum[t] = red[t][0] + 1e-16f;
    __syncthreads();
    float i0 = 1.f / ssum[0], i1 = 1.f / ssum[1], i2 = 1.f / ssum[2];

    // pass 3: aggregate
    float a_hs = 0;
    float aE0 = 0, aE1 = 0, aE2 = 0;
    float as0 = 0, as1 = 0, as2 = 0;
    for (int j = s; j < e; j++) {
        int id = perm[j];
        float al0 = expf(logits[id * 3 + 0] - m0) * i0;
        float al1 = expf(logits[id * 3 + 1] - m1) * i1;
        float al2 = expf(logits[id * 3 + 2] - m2) * i2;
        int r = row[id];
        const float* hp = &H[(size_t)r * 384];
        a_hs += al0 * hp[t] + al1 * hp[128 + t] + al2 * hp[256 + t];
        if (t < fe) {
            float v = ef[(size_t)id * fe + t];
            if (mu) {
                float w = attn[id];
                if (oneminus) w = 1.f - w;
                v = (w * v - mu[t]) * inv[t] + 1e-4f;
            }
            aE0 += al0 * v; aE1 += al1 * v; aE2 += al2 * v;
        }
        as0 += al0; as1 += al1; as2 += al2;
    }
    agghs[(size_t)n * 128 + t] = a_hs;
    if (t < fe) {
        aggE[(size_t)n * 3 * fe + 0 * fe + t] = aE0;
        aggE[(size_t)n * 3 * fe + 1 * fe + t] = aE1;
        aggE[(size_t)n * 3 * fe + 2 * fe + t] = aE2;
    }
    if (t == 0) {
        asum[n * 3 + 0] = as0;
        asum[n * 3 + 1] = as1;
        asum[n * 3 + 2] = as2;
    }
}

// ------------------------------------------------------------------ generic SGEMM, 64x64x16
// mode 0: C = A@B + bias(p0)[n]
// mode 1: C = relu((A@B + agghs(p0)[m,n] + sum_h asum(p1)[m,h]*b1(p2)[h,n]) / 3)     (N==128)
// mode 2: C = relu(A@B + b1m(p0)[n] + hm(p1)[row[m],n] + hm(p1)[col[m],n])           (N==128)
__global__ void k_gemm(const float* __restrict__ A, const float* __restrict__ B,
                       float* __restrict__ C, int M, int N, int K, int mode,
                       const float* __restrict__ p0, const float* __restrict__ p1,
                       const float* __restrict__ p2,
                       const int* __restrict__ ridx, const int* __restrict__ cidx) {
    __shared__ float As[16][64];
    __shared__ float Bs[16][68];
    int bm = blockIdx.y * 64, bn = blockIdx.x * 64;
    int tid = threadIdx.x;
    int ty = tid >> 4, tx = tid & 15;
    float acc[4][4] = {};
    int am = tid >> 2;
    int ak = (tid & 3) * 4;
    int bk = tid >> 4;
    int bn4 = (tid & 15) * 4;
    for (int k0 = 0; k0 < K; k0 += 16) {
        int arow = bm + am;
        float4 av = make_float4(0.f, 0.f, 0.f, 0.f);
        if (arow < M) av = *(const float4*)&A[(size_t)arow * K + k0 + ak];
        As[ak + 0][am] = av.x; As[ak + 1][am] = av.y;
        As[ak + 2][am] = av.z; As[ak + 3][am] = av.w;
        float4 bv = *(const float4*)&B[(size_t)(k0 + bk) * N + bn + bn4];
        *(float4*)&Bs[bk][bn4] = bv;
        __syncthreads();
        #pragma unroll
        for (int k = 0; k < 16; k++) {
            float a[4], b[4];
            #pragma unroll
            for (int i = 0; i < 4; i++) a[i] = As[k][ty * 4 + i];
            #pragma unroll
            for (int j = 0; j < 4; j++) b[j] = Bs[k][tx * 4 + j];
            #pragma unroll
            for (int i = 0; i < 4; i++)
                #pragma unroll
                for (int j = 0; j < 4; j++) acc[i][j] += a[i] * b[j];
        }
        __syncthreads();
    }
    #pragma unroll
    for (int i = 0; i < 4; i++) {
        int m = bm + ty * 4 + i;
        if (m >= M) continue;
        int r = 0, c = 0;
        if (mode == 2) { r = ridx[m]; c = cidx[m]; }
        #pragma unroll
        for (int j = 0; j < 4; j++) {
            int n = bn + tx * 4 + j;
            float v = acc[i][j];
            if (mode == 0) {
                v += p0[n];
            } else if (mode == 1) {
                v += p0[(size_t)m * 128 + n];
                v += p1[m * 3 + 0] * p2[n] + p1[m * 3 + 1] * p2[128 + n] +
                     p1[m * 3 + 2] * p2[256 + n];
                v *= (1.f / 3.f);
                v = fmaxf(v, 0.f);
            } else {
                v += p0[n];
                v += p1[(size_t)r * 128 + n] + p1[(size_t)c * 128 + n];
                v = fmaxf(v, 0.f);
            }
            C[(size_t)m * N + n] = v;
        }
    }
}

// ------------------------------------------------------------------ node attention split
__global__ void k_natt(const float* __restrict__ x, const float* __restrict__ W,
                       const float* __restrict__ b, float* __restrict__ xc,
                       float* __restrict__ xo) {
    int n = blockIdx.x * (blockDim.x >> 5) + (threadIdx.x >> 5);
    int lane = threadIdx.x & 31;
    if (n >= NN) return;
    float d0 = 0, d1 = 0;
    for (int i = lane; i < 128; i += 32) {
        float v = x[(size_t)n * 128 + i];
        d0 += v * W[i * 2 + 0];
        d1 += v * W[i * 2 + 1];
    }
    #pragma unroll
    for (int o = 16; o > 0; o >>= 1) {
        d0 += __shfl_xor_sync(0xffffffffu, d0, o);
        d1 += __shfl_xor_sync(0xffffffffu, d1, o);
    }
    d0 += b[0]; d1 += b[1];
    float mx = fmaxf(d0, d1);
    float e0 = expf(d0 - mx), e1 = expf(d1 - mx);
    float inv = 1.f / (e0 + e1);
    float n0 = e0 * inv, n1 = e1 * inv;
    for (int i = lane; i < 128; i += 32) {
        float v = x[(size_t)n * 128 + i];
        xc[(size_t)n * 128 + i] = n0 * v;
        xo[(size_t)n * 128 + i] = n1 * v;
    }
}

// ------------------------------------------------------------------ graph pooling
__global__ void k_segsum(const float* __restrict__ x, const int* __restrict__ batch,
                         float* __restrict__ g) {
    int i = blockIdx.x * blockDim.x + threadIdx.x;
    if (i < NN * 128) {
        int n = i >> 7;
        atomicAdd(&g[(size_t)batch[n] * 128 + (i & 127)], x[i]);
    }
}

// ------------------------------------------------------------------ readout (3 blocks)
__global__ void k_readout(const float* __restrict__ gc, const float* __restrict__ go,
                          const float* __restrict__ W1s, const float* __restrict__ b1s,
                          const float* __restrict__ W2s, const float* __restrict__ b2s,
                          float* __restrict__ out) {
    int which = blockIdx.x, t = threadIdx.x;
    __shared__ float M[64][129];
    __shared__ float Z[64][12];
    const float* W1 = W1s + which * 16384;
    const float* B1 = b1s + which * 128;
    const float* W2 = W2s + which * 1280;
    const float* B2 = b2s + which * 10;

    double s = 0, s2 = 0;
    for (int r = 0; r < 64; r++) {
        float v = (which == 0) ? gc[r * 128 + t]
                : (which == 1) ? go[r * 128 + t]
                               : gc[r * 128 + t] + go[r * 128 + t];
        s += v; s2 += (double)v * v;
    }
    double mud = s / 64.0;
    float mu = (float)mud;
    float iv = (float)rsqrt(s2 / 64.0 - mud * mud + 1e-5);
    for (int r = 0; r < 64; r++) {
        float v = (which == 0) ? gc[r * 128 + t]
                : (which == 1) ? go[r * 128 + t]
                               : gc[r * 128 + t] + go[r * 128 + t];
        M[r][t] = (v - mu) * iv + 1e-4f;
    }
    __syncthreads();

    float y[64];
    for (int r = 0; r < 64; r++) {
        float acc = B1[t];
        for (int k = 0; k < 128; k++) acc += M[r][k] * W1[k * 128 + t];
        y[r] = fmaxf(acc, 0.f);
    }
    s = 0; s2 = 0;
    for (int r = 0; r < 64; r++) { s += y[r]; s2 += (double)y[r] * y[r]; }
    mud = s / 64.0;
    mu = (float)mud;
    iv = (float)rsqrt(s2 / 64.0 - mud * mud + 1e-5);
    __syncthreads();
    for (int r = 0; r < 64; r++) M[r][t] = (y[r] - mu) * iv + 1e-4f;
    __syncthreads();

    if (t < 10) {
        for (int r = 0; r < 64; r++) {
            float acc = B2[t];
            for (int k = 0; k < 128; k++) acc += M[r][k] * W2[k * 10 + t];
            Z[r][t] = acc;
        }
    }
    __syncthreads();
    if (t < 64) {
        float mx = -1e30f;
        for (int c = 0; c < 10; c++) mx = fmaxf(mx, Z[t][c]);
        float sm = 0;
        for (int c = 0; c < 10; c++) sm += expf(Z[t][c] - mx);
        float l = mx + logf(sm);
        for (int c = 0; c < 10; c++) out[which * 640 + t * 10 + c] = Z[t][c] - l;
    }
}

// ------------------------------------------------------------------ host-side layer driver
static void run_layer(float* F, double* DS,
                      const float* xin, const float* ef, int fe,
                      const float* Wn, const float* We, const float* bb, const float* aa,
                      const int* row, const int* col, const int* offs, const int* perm,
                      float* xout, float* eout,
                      const float* attn, int oneminus, const float* mu, const float* inv,
                      float* eattn) {
    cudaMemsetAsync(DS, 0, 256 * sizeof(double), 0);
    k_colstat<<<128, 128>>>(xin, NN, DS);
    k_bnfin<<<1, 128>>>(DS, NN, F + O_MU, F + O_INV);
    k_bnapply<<<(NN * 128 + 255) / 256, 256>>>(xin, F + O_MU, F + O_INV, F + O_XB, NN);
    k_gemm<<<dim3(6, (NN + 63) / 64), 256>>>(F + O_XB, Wn, F + O_H, NN, 384, 128, 0,
                                             bb, nullptr, nullptr, nullptr, nullptr);
    k_nodescore<<<NN, 128>>>(F + O_H, aa, F + O_SSRC, F + O_SDST, F + O_HM);
    k_wprep<<<(3 * fe * 128 + 255) / 256, 256>>>(We, bb + 384, aa + 768, fe,
                                                 eout ? 1 : 0, F + O_A2, F + O_C2,
                                                 F + O_WEM, F + O_B1M, F + O_WPERM);
    k_edgelogit<<<NE / 8, 256>>>(ef, fe, row, col, F + O_SSRC, F + O_SDST,
                                 F + O_A2, F + O_C2, attn, oneminus, mu, inv,
                                 F + O_LOG, eattn, eattn ? 1 : 0);
    k_nodeagg<<<NN, 128>>>(offs, perm, row, F + O_LOG, F + O_H, ef, fe,
                           attn, oneminus, mu, inv,
                           F + O_AGGHS, F + O_AGGE, F + O_ASUM);
    k_gemm<<<dim3(2, (NN + 63) / 64), 256>>>(F + O_AGGE, F + O_WPERM, xout,
                                             NN, 128, 3 * fe, 1,
                                             F + O_AGGHS, F + O_ASUM, bb + 384,
                                             nullptr, nullptr);
    if (eout)
        k_gemm<<<dim3(2, (NE + 63) / 64), 256>>>(ef, F + O_WEM, eout, NE, 128, fe, 2,
                                                 F + O_B1M, F + O_HM, nullptr, row, col);
}

extern "C" void kernel_launch(void* const* d_in, const int* in_sizes, int n_in,
                              void* d_out, int out_size) {
    float* F; cudaGetSymbolAddress((void**)&F, g_f);
    double* DS; cudaGetSymbolAddress((void**)&DS, g_d);
    int* I; cudaGetSymbolAddress((void**)&I, g_i);

    const float* x     = (const float*)d_in[0];
    const float* eattr = (const float*)d_in[1];
    const float* Wn0   = (const float*)d_in[2];
    const float* We0   = (const float*)d_in[3];
    const float* b0    = (const float*)d_in[4];
    const float* a0    = (const float*)d_in[5];
    const float* Wn    = (const float*)d_in[6];
    const float* We    = (const float*)d_in[7];
    const float* bb    = (const float*)d_in[8];
    const float* aa    = (const float*)d_in[9];
    const float* nattW = (const float*)d_in[10];
    const float* nattB = (const float*)d_in[11];
    const float* fcW1  = (const float*)d_in[12];
    const float* fcb1  = (const float*)d_in[13];
    const float* fcW2  = (const float*)d_in[14];
    const float* fcb2  = (const float*)d_in[15];
    const int* eidx    = (const int*)d_in[16];
    const int* batch   = (const int*)d_in[17];
    const int* row = eidx;
    const int* col = eidx + NE;

    int* CNT = I;
    int* OFFS = I + 10000;
    int* FILL = I + 20001;
    int* PERM = I + 30001;

    // CSR by destination (reused by all 6 layers)
    cudaMemsetAsync(CNT, 0, NN * sizeof(int), 0);
    k_count<<<(NE + 255) / 256, 256>>>(col, CNT);
    k_scan<<<1, 1024>>>(CNT, OFFS);
    cudaMemcpyAsync(FILL, OFFS, NN * sizeof(int), cudaMemcpyDeviceToDevice, 0);
    k_fill<<<(NE + 255) / 256, 256>>>(col, FILL, PERM);

    // layer 0: fe=16
    run_layer(F, DS, x, eattr, 16, Wn0, We0, b0, a0, row, col, OFFS, PERM,
              F + O_X1, F + O_EA, nullptr, 0, nullptr, nullptr, nullptr);
    // loop layers 1..3 (weights idx 0..2)
    run_layer(F, DS, F + O_X1, F + O_EA, 128, Wn, We, bb, aa, row, col, OFFS, PERM,
              F + O_X1, F + O_EB, nullptr, 0, nullptr, nullptr, nullptr);
    run_layer(F, DS, F + O_X1, F + O_EB, 128, Wn + 49152, We + 49152, bb + 768, aa + 1152,
              row, col, OFFS, PERM, F + O_X1, F + O_EA, nullptr, 0, nullptr, nullptr, nullptr);
    run_layer(F, DS, F + O_X1, F + O_EA, 128, Wn + 2 * 49152, We + 2 * 49152,
              bb + 2 * 768, aa + 2 * 1152, row, col, OFFS, PERM,
              F + O_X1, F + O_EB, nullptr, 0, nullptr, nullptr, F + O_EATTN);

    // node attention split
    k_natt<<<(NN + 7) / 8, 256>>>(F + O_X1, nattW, nattB, F + O_XC, F + O_XO);

    // edge_c / edge_o BN moments (folded transform, no materialization)
    cudaMemsetAsync(DS, 0, 512 * sizeof(double), 0);
    k_edgemom<<<256, 128>>>(F + O_EB, F + O_EATTN, DS);
    k_edgemomfin<<<1, 128>>>(DS, F + O_MUC, F + O_INVC, F + O_MUO, F + O_INVO);

    // causal / non-causal branches (weights idx 3 / 4), no e_out
    run_layer(F, DS, F + O_XC, F + O_EB, 128, Wn + 3 * 49152, We + 3 * 49152,
              bb + 3 * 768, aa + 3 * 1152, row, col, OFFS, PERM,
              F + O_XC, nullptr, F + O_EATTN, 0, F + O_MUC, F + O_INVC, nullptr);
    run_layer(F, DS, F + O_XO, F + O_EB, 128, Wn + 4 * 49152, We + 4 * 49152,
              bb + 4 * 768, aa + 4 * 1152, row, col, OFFS, PERM,
              F + O_XO, nullptr, F + O_EATTN, 1, F + O_MUO, F + O_INVO, nullptr);

    // graph pooling
    cudaMemsetAsync(F + O_GC, 0, 2 * NG * 128 * sizeof(float), 0);
    k_segsum<<<(NN * 128 + 255) / 256, 256>>>(F + O_XC, batch, F + O_GC);
    k_segsum<<<(NN * 128 + 255) / 256, 256>>>(F + O_XO, batch, F + O_GO);

    // readouts
    k_readout<<<3, 128>>>(F + O_GC, F + O_GO, fcW1, fcb1, fcW2, fcb2, (float*)d_out);
}

// round 3
// speedup vs baseline: 1.1633x; 1.1633x over previous
#include <cuda_runtime.h>
#include <math.h>

#define NN 10000
#define NE 160000
#define NG 64

// ------------------------------------------------------------------ scratch
__device__ __align__(128) float g_f[57200000];
__device__ double g_d[512];
__device__ int    g_i[200032];

// float offsets
#define O_EA    0UL
#define O_EB    20480000UL
#define O_H     40960000UL
#define O_X1    44800000UL
#define O_XB    46080000UL
#define O_XC    47360000UL
#define O_XO    48640000UL
#define O_AGGE  49920000UL
#define O_AGGHS 53760000UL
#define O_HM    55040000UL
#define O_LOG   56320000UL
#define O_EATTN 56800000UL
#define O_SSRC  56960000UL
#define O_SDST  56990000UL
#define O_ASUM  57020000UL
#define O_WPERM 57050000UL
#define O_A2    57099152UL
#define O_C2    57099536UL
#define O_WEM   57099540UL
#define O_B1M   57115924UL
#define O_MU    57116052UL
#define O_INV   57116180UL
#define O_MUC   57116308UL
#define O_INVC  57116436UL
#define O_MUO   57116564UL
#define O_INVO  57116692UL
#define O_GC    57116820UL
#define O_GO    57125012UL

// ------------------------------------------------------------------ CSR build
__global__ void k_count(const int* __restrict__ col, int* __restrict__ cnt) {
    int i = blockIdx.x * blockDim.x + threadIdx.x;
    if (i < NE) atomicAdd(&cnt[col[i]], 1);
}

__global__ void k_scan(const int* __restrict__ cnt, int* __restrict__ offs) {
    __shared__ int sm[1024];
    int t = threadIdx.x;
    const int per = (NN + 1023) / 1024;
    int b = t * per, e = min(NN, b + per);
    int s = 0;
    for (int i = b; i < e; i++) s += cnt[i];
    sm[t] = s;
    __syncthreads();
    for (int o = 1; o < 1024; o <<= 1) {
        int v = (t >= o) ? sm[t - o] : 0;
        __syncthreads();
        sm[t] += v;
        __syncthreads();
    }
    int base = (t == 0) ? 0 : sm[t - 1];
    for (int i = b; i < e; i++) { offs[i] = base; base += cnt[i]; }
    if (t == 1023) offs[NN] = sm[1023];
}

__global__ void k_fill(const int* __restrict__ col, int* __restrict__ fill,
                       int* __restrict__ perm) {
    int i = blockIdx.x * blockDim.x + threadIdx.x;
    if (i < NE) { int p = atomicAdd(&fill[col[i]], 1); perm[p] = i; }
}

// ------------------------------------------------------------------ BN (node features)
__global__ void k_colstat(const float* __restrict__ X, int rows, double* __restrict__ sums) {
    int c = threadIdx.x;  // 128
    double s = 0, s2 = 0;
    #pragma unroll 4
    for (int r = blockIdx.x; r < rows; r += gridDim.x) {
        float v = X[(size_t)r * 128 + c];
        s += v; s2 += (double)v * v;
    }
    atomicAdd(&sums[c], s);
    atomicAdd(&sums[128 + c], s2);
}

__global__ void k_bnfin(const double* __restrict__ sums, int rows,
                        float* __restrict__ mu, float* __restrict__ inv) {
    int c = threadIdx.x;
    double m = sums[c] / rows;
    double v = sums[128 + c] / rows - m * m;
    mu[c] = (float)m;
    inv[c] = (float)rsqrt(v + 1e-5);
}

__global__ void k_bnapply(const float* __restrict__ X, const float* __restrict__ mu,
                          const float* __restrict__ inv, float* __restrict__ Y, int rows) {
    int i = blockIdx.x * blockDim.x + threadIdx.x;
    if (i < rows * 128) {
        int c = i & 127;
        Y[i] = (X[i] - mu[c]) * inv[c] + 1e-4f;
    }
}

// BN moments of edge_c = attn*e and edge_o = (1-attn)*e in one pass
__global__ void k_edgemom(const float* __restrict__ E4, const float* __restrict__ attn,
                          double* __restrict__ sums) {
    int t = threadIdx.x;  // 128
    double sc = 0, sc2 = 0, so = 0, so2 = 0;
    #pragma unroll 4
    for (int r = blockIdx.x; r < NE; r += gridDim.x) {
        float w = attn[r];
        float v = E4[(size_t)r * 128 + t];
        float tc = w * v, to = (1.f - w) * v;
        sc += tc; sc2 += (double)tc * tc;
        so += to; so2 += (double)to * to;
    }
    atomicAdd(&sums[t], sc);
    atomicAdd(&sums[128 + t], sc2);
    atomicAdd(&sums[256 + t], so);
    atomicAdd(&sums[384 + t], so2);
}

__global__ void k_edgemomfin(const double* __restrict__ sums,
                             float* __restrict__ muc, float* __restrict__ invc,
                             float* __restrict__ muo, float* __restrict__ invo) {
    int c = threadIdx.x;
    double m = sums[c] / NE, v = sums[128 + c] / NE - m * m;
    muc[c] = (float)m; invc[c] = (float)rsqrt(v + 1e-5);
    m = sums[256 + c] / NE; v = sums[384 + c] / NE - m * m;
    muo[c] = (float)m; invo[c] = (float)rsqrt(v + 1e-5);
}

// ------------------------------------------------------------------ per-layer weight prep
__global__ void k_wprep(const float* __restrict__ We, const float* __restrict__ b1,
                        const float* __restrict__ a2, int fe, int need_em,
                        float* __restrict__ A2, float* __restrict__ C2,
                        float* __restrict__ WeM, float* __restrict__ B1M,
                        float* __restrict__ Wperm) {
    int i = blockIdx.x * blockDim.x + threadIdx.x;
    if (i < fe * 3) {
        int f = i / 3, h = i % 3;
        float s = 0;
        for (int d = 0; d < 128; d++) s += We[(size_t)(f * 3 + h) * 128 + d] * a2[h * 128 + d];
        A2[i] = s;
    }
    if (i < 3) {
        float s = 0;
        for (int d = 0; d < 128; d++) s += b1[i * 128 + d] * a2[i * 128 + d];
        C2[i] = s;
    }
    if (i < 128) B1M[i] = (b1[i] + b1[128 + i] + b1[256 + i]) * (1.f / 3.f);
    if (need_em && i < fe * 128) {
        int f = i / 128, d = i % 128;
        WeM[i] = (We[(size_t)(f * 3) * 128 + d] + We[(size_t)(f * 3 + 1) * 128 + d] +
                  We[(size_t)(f * 3 + 2) * 128 + d]) * (1.f / 3.f);
    }
    if (i < 3 * fe * 128) {
        int hi = i / 128, d = i % 128;
        int h = hi / fe, f = hi % fe;
        Wperm[i] = We[(size_t)(f * 3 + h) * 128 + d];
    }
}

// ------------------------------------------------------------------ node scores from H
__global__ void k_nodescore(const float* __restrict__ H, const float* __restrict__ a,
                            float* __restrict__ ssrc, float* __restrict__ sdst,
                            float* __restrict__ hm) {
    __shared__ float red[6][128];
    int n = blockIdx.x, t = threadIdx.x;
    float h0 = H[(size_t)n * 384 + t];
    float h1 = H[(size_t)n * 384 + 128 + t];
    float h2 = H[(size_t)n * 384 + 256 + t];
    hm[(size_t)n * 128 + t] = (h0 + h1 + h2) * (1.f / 3.f);
    red[0][t] = h0 * a[t];       red[1][t] = h1 * a[128 + t]; red[2][t] = h2 * a[256 + t];
    red[3][t] = h0 * a[384 + t]; red[4][t] = h1 * a[512 + t]; red[5][t] = h2 * a[640 + t];
    __syncthreads();
    for (int o = 64; o > 0; o >>= 1) {
        if (t < o) {
            #pragma unroll
            for (int q = 0; q < 6; q++) red[q][t] += red[q][t + o];
        }
        __syncthreads();
    }
    if (t < 3) {
        ssrc[n * 3 + t] = red[t][0];
        sdst[n * 3 + t] = red[3 + t][0];
    }
}

// ------------------------------------------------------------------ edge logits (warp/edge)
__global__ void k_edgelogit(const float* __restrict__ ef, int fe,
                            const int* __restrict__ row, const int* __restrict__ colv,
                            const float* __restrict__ ssrc, const float* __restrict__ sdst,
                            const float* __restrict__ A2, const float* __restrict__ C2,
                            const float* __restrict__ attn, int oneminus,
                            const float* __restrict__ mu, const float* __restrict__ inv,
                            float* __restrict__ logits, float* __restrict__ eattn, int do_attn) {
    int gw = (blockIdx.x * blockDim.x + threadIdx.x) >> 5;
    int lane = threadIdx.x & 31;
    if (gw >= NE) return;
    float w = 1.f;
    if (attn) { w = attn[gw]; if (oneminus) w = 1.f - w; }
    float p0 = 0, p1 = 0, p2 = 0;
    for (int i = lane; i < fe; i += 32) {
        float v = ef[(size_t)gw * fe + i];
        if (mu) v = (w * v - mu[i]) * inv[i] + 1e-4f;
        p0 += v * A2[i * 3 + 0];
        p1 += v * A2[i * 3 + 1];
        p2 += v * A2[i * 3 + 2];
    }
    #pragma unroll
    for (int o = 16; o > 0; o >>= 1) {
        p0 += __shfl_down_sync(0xffffffffu, p0, o);
        p1 += __shfl_down_sync(0xffffffffu, p1, o);
        p2 += __shfl_down_sync(0xffffffffu, p2, o);
    }
    if (lane == 0) {
        int r = row[gw], c = colv[gw];
        float l0 = ssrc[r * 3 + 0] + sdst[c * 3 + 0] + p0 + C2[0];
        float l1 = ssrc[r * 3 + 1] + sdst[c * 3 + 1] + p1 + C2[1];
        float l2 = ssrc[r * 3 + 2] + sdst[c * 3 + 2] + p2 + C2[2];
        l0 = l0 > 0.f ? l0 : 0.2f * l0;
        l1 = l1 > 0.f ? l1 : 0.2f * l1;
        l2 = l2 > 0.f ? l2 : 0.2f * l2;
        logits[gw * 3 + 0] = l0;
        logits[gw * 3 + 1] = l1;
        logits[gw * 3 + 2] = l2;
        if (do_attn) {
            float m = (l0 + l1 + l2) * (1.f / 3.f);
            eattn[gw] = 1.f / (1.f + expf(-m));
        }
    }
}

// ------------------------------------------------------------------ per-node softmax + aggregation
__global__ void k_nodeagg(const int* __restrict__ offs, const int* __restrict__ perm,
                          const int* __restrict__ row,
                          const float* __restrict__ logits, const float* __restrict__ H,
                          const float* __restrict__ ef, int fe,
                          const float* __restrict__ attn, int oneminus,
                          const float* __restrict__ mu, const float* __restrict__ inv,
                          float* __restrict__ agghs, float* __restrict__ aggE,
                          float* __restrict__ asum) {
    __shared__ float red[3][128];
    __shared__ float smax[3], ssum[3];
    int n = blockIdx.x, t = threadIdx.x;
    int s = offs[n], e = offs[n + 1];

    float mx0 = -1e30f, mx1 = -1e30f, mx2 = -1e30f;
    for (int j = s + t; j < e; j += 128) {
        int id = perm[j];
        mx0 = fmaxf(mx0, logits[id * 3 + 0]);
        mx1 = fmaxf(mx1, logits[id * 3 + 1]);
        mx2 = fmaxf(mx2, logits[id * 3 + 2]);
    }
    red[0][t] = mx0; red[1][t] = mx1; red[2][t] = mx2;
    __syncthreads();
    for (int o = 64; o > 0; o >>= 1) {
        if (t < o) {
            red[0][t] = fmaxf(red[0][t], red[0][t + o]);
            red[1][t] = fmaxf(red[1][t], red[1][t + o]);
            red[2][t] = fmaxf(red[2][t], red[2][t + o]);
        }
        __syncthreads();
    }
    if (t < 3) smax[t] = red[t][0];
    __syncthreads();
    float m0 = smax[0], m1 = smax[1], m2 = smax[2];

    float sm0 = 0, sm1 = 0, sm2 = 0;
    for (int j = s + t; j < e; j += 128) {
        int id = perm[j];
        sm0 += expf(logits[id * 3 + 0] - m0);
        sm1 += expf(logits[id * 3 + 1] - m1);
        sm2 += expf(logits[id * 3 + 2] - m2);
    }
    red[0][t] = sm0; red[1][t] = sm1; red[2][t] = sm2;
    __syncthreads();
    for (int o = 64; o > 0; o >>= 1) {
        if (t < o) {
            red[0][t] += red[0][t + o];
            red[1][t] += red[1][t + o];
            red[2][t] += red[2][t + o];
        }
        __syncthreads();
    }
    if (t < 3) ssum[t] = red[t][0] + 1e-16f;
    __syncthreads();
    float i0 = 1.f / ssum[0], i1 = 1.f / ssum[1], i2 = 1.f / ssum[2];

    float a_hs = 0;
    float aE0 = 0, aE1 = 0, aE2 = 0;
    float as0 = 0, as1 = 0, as2 = 0;
    for (int j = s; j < e; j++) {
        int id = perm[j];
        float al0 = expf(logits[id * 3 + 0] - m0) * i0;
        float al1 = expf(logits[id * 3 + 1] - m1) * i1;
        float al2 = expf(logits[id * 3 + 2] - m2) * i2;
        int r = row[id];
        const float* hp = &H[(size_t)r * 384];
        a_hs += al0 * hp[t] + al1 * hp[128 + t] + al2 * hp[256 + t];
        if (t < fe) {
            float v = ef[(size_t)id * fe + t];
            if (mu) {
                float w = attn[id];
                if (oneminus) w = 1.f - w;
                v = (w * v - mu[t]) * inv[t] + 1e-4f;
            }
            aE0 += al0 * v; aE1 += al1 * v; aE2 += al2 * v;
        }
        as0 += al0; as1 += al1; as2 += al2;
    }
    agghs[(size_t)n * 128 + t] = a_hs;
    if (t < fe) {
        aggE[(size_t)n * 3 * fe + 0 * fe + t] = aE0;
        aggE[(size_t)n * 3 * fe + 1 * fe + t] = aE1;
        aggE[(size_t)n * 3 * fe + 2 * fe + t] = aE2;
    }
    if (t == 0) {
        asum[n * 3 + 0] = as0;
        asum[n * 3 + 1] = as1;
        asum[n * 3 + 2] = as2;
    }
}

// ------------------------------------------------------------------ SGEMM 128x128x16, 8x8 microtile
// mode 0: C = A@B + bias(p0)[n]
// mode 1: C = relu((A@B + agghs(p0)[m,n] + sum_h asum(p1)[m,h]*b1(p2)[h,n]) / 3)     (N==128)
// mode 2: C = relu(A@B + b1m(p0)[n] + hm(p1)[row[m],n] + hm(p1)[col[m],n])           (N==128)
__global__ void __launch_bounds__(256, 2)
k_gemm(const float* __restrict__ A, const float* __restrict__ B,
       float* __restrict__ C, int M, int N, int K, int mode,
       const float* __restrict__ p0, const float* __restrict__ p1,
       const float* __restrict__ p2,
       const int* __restrict__ ridx, const int* __restrict__ cidx) {
    __shared__ float As[16][128];
    __shared__ float Bs[16][128];
    int bm = blockIdx.y * 128, bn = blockIdx.x * 128;
    int tid = threadIdx.x;
    int tx = tid & 15, ty = tid >> 4;
    float acc[8][8] = {};

    for (int k0 = 0; k0 < K; k0 += 16) {
        #pragma unroll
        for (int rep = 0; rep < 2; rep++) {
            int idx = tid + rep * 256;
            int r = idx >> 2, c4 = (idx & 3) * 4;
            float4 av = make_float4(0.f, 0.f, 0.f, 0.f);
            int arow = bm + r;
            if (arow < M) av = *(const float4*)&A[(size_t)arow * K + k0 + c4];
            As[c4 + 0][r] = av.x; As[c4 + 1][r] = av.y;
            As[c4 + 2][r] = av.z; As[c4 + 3][r] = av.w;
            int br = idx >> 5, bc4 = (idx & 31) * 4;
            *(float4*)&Bs[br][bc4] = *(const float4*)&B[(size_t)(k0 + br) * N + bn + bc4];
        }
        __syncthreads();
        #pragma unroll
        for (int k = 0; k < 16; k++) {
            float a[8], b[8];
            *(float4*)&a[0] = *(const float4*)&As[k][ty * 4];
            *(float4*)&a[4] = *(const float4*)&As[k][64 + ty * 4];
            *(float4*)&b[0] = *(const float4*)&Bs[k][tx * 4];
            *(float4*)&b[4] = *(const float4*)&Bs[k][64 + tx * 4];
            #pragma unroll
            for (int i = 0; i < 8; i++)
                #pragma unroll
                for (int j = 0; j < 8; j++) acc[i][j] += a[i] * b[j];
        }
        __syncthreads();
    }

    #pragma unroll
    for (int i = 0; i < 8; i++) {
        int m = bm + ((i < 4) ? (ty * 4 + i) : (64 + ty * 4 + i - 4));
        if (m >= M) continue;
        int r = 0, c = 0;
        if (mode == 2) { r = ridx[m]; c = cidx[m]; }
        #pragma unroll
        for (int jg = 0; jg < 2; jg++) {
            int nb = bn + (jg ? (64 + tx * 4) : (tx * 4));
            float4 o;
            float* ov = &o.x;
            #pragma unroll
            for (int j = 0; j < 4; j++) {
                int n = nb + j;
                float v = acc[i][jg * 4 + j];
                if (mode == 0) {
                    v += p0[n];
                } else if (mode == 1) {
                    v += p0[(size_t)m * 128 + n];
                    v += p1[m * 3 + 0] * p2[n] + p1[m * 3 + 1] * p2[128 + n] +
                         p1[m * 3 + 2] * p2[256 + n];
                    v *= (1.f / 3.f);
                    v = fmaxf(v, 0.f);
                } else {
                    v += p0[n];
                    v += p1[(size_t)r * 128 + n] + p1[(size_t)c * 128 + n];
                    v = fmaxf(v, 0.f);
                }
                ov[j] = v;
            }
            *(float4*)&C[(size_t)m * N + nb] = o;
        }
    }
}

// ------------------------------------------------------------------ node attention split
__global__ void k_natt(const float* __restrict__ x, const float* __restrict__ W,
                       const float* __restrict__ b, float* __restrict__ xc,
                       float* __restrict__ xo) {
    int n = blockIdx.x * (blockDim.x >> 5) + (threadIdx.x >> 5);
    int lane = threadIdx.x & 31;
    if (n >= NN) return;
    float d0 = 0, d1 = 0;
    for (int i = lane; i < 128; i += 32) {
        float v = x[(size_t)n * 128 + i];
        d0 += v * W[i * 2 + 0];
        d1 += v * W[i * 2 + 1];
    }
    #pragma unroll
    for (int o = 16; o > 0; o >>= 1) {
        d0 += __shfl_xor_sync(0xffffffffu, d0, o);
        d1 += __shfl_xor_sync(0xffffffffu, d1, o);
    }
    d0 += b[0]; d1 += b[1];
    float mx = fmaxf(d0, d1);
    float e0 = expf(d0 - mx), e1 = expf(d1 - mx);
    float inv = 1.f / (e0 + e1);
    float n0 = e0 * inv, n1 = e1 * inv;
    for (int i = lane; i < 128; i += 32) {
        float v = x[(size_t)n * 128 + i];
        xc[(size_t)n * 128 + i] = n0 * v;
        xo[(size_t)n * 128 + i] = n1 * v;
    }
}

// ------------------------------------------------------------------ graph pooling
__global__ void k_segsum(const float* __restrict__ x, const int* __restrict__ batch,
                         float* __restrict__ g) {
    int i = blockIdx.x * blockDim.x + threadIdx.x;
    if (i < NN * 128) {
        int n = i >> 7;
        atomicAdd(&g[(size_t)batch[n] * 128 + (i & 127)], x[i]);
    }
}

// ------------------------------------------------------------------ readout (3 blocks)
__global__ void k_readout(const float* __restrict__ gc, const float* __restrict__ go,
                          const float* __restrict__ W1s, const float* __restrict__ b1s,
                          const float* __restrict__ W2s, const float* __restrict__ b2s,
                          float* __restrict__ out) {
    int which = blockIdx.x, t = threadIdx.x;
    __shared__ float M[64][129];
    __shared__ float Z[64][12];
    const float* W1 = W1s + which * 16384;
    const float* B1 = b1s + which * 128;
    const float* W2 = W2s + which * 1280;
    const float* B2 = b2s + which * 10;

    double s = 0, s2 = 0;
    for (int r = 0; r < 64; r++) {
        float v = (which == 0) ? gc[r * 128 + t]
                : (which == 1) ? go[r * 128 + t]
                               : gc[r * 128 + t] + go[r * 128 + t];
        s += v; s2 += (double)v * v;
    }
    double mud = s / 64.0;
    float mu = (float)mud;
    float iv = (float)rsqrt(s2 / 64.0 - mud * mud + 1e-5);
    for (int r = 0; r < 64; r++) {
        float v = (which == 0) ? gc[r * 128 + t]
                : (which == 1) ? go[r * 128 + t]
                               : gc[r * 128 + t] + go[r * 128 + t];
        M[r][t] = (v - mu) * iv + 1e-4f;
    }
    __syncthreads();

    float y[64];
    for (int r = 0; r < 64; r++) {
        float acc = B1[t];
        for (int k = 0; k < 128; k++) acc += M[r][k] * W1[k * 128 + t];
        y[r] = fmaxf(acc, 0.f);
    }
    s = 0; s2 = 0;
    for (int r = 0; r < 64; r++) { s += y[r]; s2 += (double)y[r] * y[r]; }
    mud = s / 64.0;
    mu = (float)mud;
    iv = (float)rsqrt(s2 / 64.0 - mud * mud + 1e-5);
    __syncthreads();
    for (int r = 0; r < 64; r++) M[r][t] = (y[r] - mu) * iv + 1e-4f;
    __syncthreads();

    if (t < 10) {
        for (int r = 0; r < 64; r++) {
            float acc = B2[t];
            for (int k = 0; k < 128; k++) acc += M[r][k] * W2[k * 10 + t];
            Z[r][t] = acc;
        }
    }
    __syncthreads();
    if (t < 64) {
        float mx = -1e30f;
        for (int c = 0; c < 10; c++) mx = fmaxf(mx, Z[t][c]);
        float sm = 0;
        for (int c = 0; c < 10; c++) sm += expf(Z[t][c] - mx);
        float l = mx + logf(sm);
        for (int c = 0; c < 10; c++) out[which * 640 + t * 10 + c] = Z[t][c] - l;
    }
}

// ------------------------------------------------------------------ host-side layer driver
static void run_layer(float* F, double* DS,
                      const float* xin, const float* ef, int fe,
                      const float* Wn, const float* We, const float* bb, const float* aa,
                      const int* row, const int* col, const int* offs, const int* perm,
                      float* xout, float* eout,
                      const float* attn, int oneminus, const float* mu, const float* inv,
                      float* eattn) {
    cudaMemsetAsync(DS, 0, 256 * sizeof(double), 0);
    k_colstat<<<640, 128>>>(xin, NN, DS);
    k_bnfin<<<1, 128>>>(DS, NN, F + O_MU, F + O_INV);
    k_bnapply<<<(NN * 128 + 255) / 256, 256>>>(xin, F + O_MU, F + O_INV, F + O_XB, NN);
    k_gemm<<<dim3(3, (NN + 127) / 128), 256>>>(F + O_XB, Wn, F + O_H, NN, 384, 128, 0,
                                               bb, nullptr, nullptr, nullptr, nullptr);
    k_nodescore<<<NN, 128>>>(F + O_H, aa, F + O_SSRC, F + O_SDST, F + O_HM);
    k_wprep<<<(3 * fe * 128 + 255) / 256, 256>>>(We, bb + 384, aa + 768, fe,
                                                 eout ? 1 : 0, F + O_A2, F + O_C2,
                                                 F + O_WEM, F + O_B1M, F + O_WPERM);
    k_edgelogit<<<NE / 8, 256>>>(ef, fe, row, col, F + O_SSRC, F + O_SDST,
                                 F + O_A2, F + O_C2, attn, oneminus, mu, inv,
                                 F + O_LOG, eattn, eattn ? 1 : 0);
    k_nodeagg<<<NN, 128>>>(offs, perm, row, F + O_LOG, F + O_H, ef, fe,
                           attn, oneminus, mu, inv,
                           F + O_AGGHS, F + O_AGGE, F + O_ASUM);
    k_gemm<<<dim3(1, (NN + 127) / 128), 256>>>(F + O_AGGE, F + O_WPERM, xout,
                                               NN, 128, 3 * fe, 1,
                                               F + O_AGGHS, F + O_ASUM, bb + 384,
                                               nullptr, nullptr);
    if (eout)
        k_gemm<<<dim3(1, (NE + 127) / 128), 256>>>(ef, F + O_WEM, eout, NE, 128, fe, 2,
                                                   F + O_B1M, F + O_HM, nullptr, row, col);
}

extern "C" void kernel_launch(void* const* d_in, const int* in_sizes, int n_in,
                              void* d_out, int out_size) {
    float* F; cudaGetSymbolAddress((void**)&F, g_f);
    double* DS; cudaGetSymbolAddress((void**)&DS, g_d);
    int* I; cudaGetSymbolAddress((void**)&I, g_i);

    const float* x     = (const float*)d_in[0];
    const float* eattr = (const float*)d_in[1];
    const float* Wn0   = (const float*)d_in[2];
    const float* We0   = (const float*)d_in[3];
    const float* b0    = (const float*)d_in[4];
    const float* a0    = (const float*)d_in[5];
    const float* Wn    = (const float*)d_in[6];
    const float* We    = (const float*)d_in[7];
    const float* bb    = (const float*)d_in[8];
    const float* aa    = (const float*)d_in[9];
    const float* nattW = (const float*)d_in[10];
    const float* nattB = (const float*)d_in[11];
    const float* fcW1  = (const float*)d_in[12];
    const float* fcb1  = (const float*)d_in[13];
    const float* fcW2  = (const float*)d_in[14];
    const float* fcb2  = (const float*)d_in[15];
    const int* eidx    = (const int*)d_in[16];
    const int* batch   = (const int*)d_in[17];
    const int* row = eidx;
    const int* col = eidx + NE;

    int* CNT = I;
    int* OFFS = I + 10000;
    int* FILL = I + 20001;
    int* PERM = I + 30001;

    // CSR by destination (reused by all 6 layers)
    cudaMemsetAsync(CNT, 0, NN * sizeof(int), 0);
    k_count<<<(NE + 255) / 256, 256>>>(col, CNT);
    k_scan<<<1, 1024>>>(CNT, OFFS);
    cudaMemcpyAsync(FILL, OFFS, NN * sizeof(int), cudaMemcpyDeviceToDevice, 0);
    k_fill<<<(NE + 255) / 256, 256>>>(col, FILL, PERM);

    // layer 0: fe=16
    run_layer(F, DS, x, eattr, 16, Wn0, We0, b0, a0, row, col, OFFS, PERM,
              F + O_X1, F + O_EA, nullptr, 0, nullptr, nullptr, nullptr);
    // loop layers 1..3 (weights idx 0..2)
    run_layer(F, DS, F + O_X1, F + O_EA, 128, Wn, We, bb, aa, row, col, OFFS, PERM,
              F + O_X1, F + O_EB, nullptr, 0, nullptr, nullptr, nullptr);
    run_layer(F, DS, F + O_X1, F + O_EB, 128, Wn + 49152, We + 49152, bb + 768, aa + 1152,
              row, col, OFFS, PERM, F + O_X1, F + O_EA, nullptr, 0, nullptr, nullptr, nullptr);
    run_layer(F, DS, F + O_X1, F + O_EA, 128, Wn + 2 * 49152, We + 2 * 49152,
              bb + 2 * 768, aa + 2 * 1152, row, col, OFFS, PERM,
              F + O_X1, F + O_EB, nullptr, 0, nullptr, nullptr, F + O_EATTN);

    // node attention split
    k_natt<<<(NN + 7) / 8, 256>>>(F + O_X1, nattW, nattB, F + O_XC, F + O_XO);

    // edge_c / edge_o BN moments (folded transform, no materialization)
    cudaMemsetAsync(DS, 0, 512 * sizeof(double), 0);
    k_edgemom<<<1024, 128>>>(F + O_EB, F + O_EATTN, DS);
    k_edgemomfin<<<1, 128>>>(DS, F + O_MUC, F + O_INVC, F + O_MUO, F + O_INVO);

    // causal / non-causal branches (weights idx 3 / 4), no e_out
    run_layer(F, DS, F + O_XC, F + O_EB, 128, Wn + 3 * 49152, We + 3 * 49152,
              bb + 3 * 768, aa + 3 * 1152, row, col, OFFS, PERM,
              F + O_XC, nullptr, F + O_EATTN, 0, F + O_MUC, F + O_INVC, nullptr);
    run_layer(F, DS, F + O_XO, F + O_EB, 128, Wn + 4 * 49152, We + 4 * 49152,
              bb + 4 * 768, aa + 4 * 1152, row, col, OFFS, PERM,
              F + O_XO, nullptr, F + O_EATTN, 1, F + O_MUO, F + O_INVO, nullptr);

    // graph pooling
    cudaMemsetAsync(F + O_GC, 0, 2 * NG * 128 * sizeof(float), 0);
    k_segsum<<<(NN * 128 + 255) / 256, 256>>>(F + O_XC, batch, F + O_GC);
    k_segsum<<<(NN * 128 + 255) / 256, 256>>>(F + O_XO, batch, F + O_GO);

    // readouts
    k_readout<<<3, 128>>>(F + O_GC, F + O_GO, fcW1, fcb1, fcW2, fcb2, (float*)d_out);
}

// round 4
// speedup vs baseline: 1.1861x; 1.0196x over previous
#include <cuda_runtime.h>
#include <math.h>

#define NN 10000
#define NE 160000
#define NG 64

// ------------------------------------------------------------------ scratch
__device__ __align__(128) float g_f[57200000];
__device__ double g_d[512];
__device__ int    g_i[520064];

// float offsets
#define O_EA    0UL
#define O_EB    20480000UL
#define O_H     40960000UL
#define O_X1    44800000UL
#define O_ATTNP 46080000UL
#define O_XC    47360000UL
#define O_XO    48640000UL
#define O_AGGE  49920000UL
#define O_AGGHS 53760000UL
#define O_HM    55040000UL
#define O_LOG   56320000UL
#define O_EATTN 56800000UL
#define O_SSRC  56960000UL
#define O_SDST  56990000UL
#define O_ASUM  57020000UL
#define O_WPERM 57050000UL
#define O_A2    57099152UL
#define O_C2    57099536UL
#define O_WEM   57099540UL
#define O_B1M   57115924UL
#define O_MU    57116052UL
#define O_INV   57116180UL
#define O_MUC   57116308UL
#define O_INVC  57116436UL
#define O_MUO   57116564UL
#define O_INVO  57116692UL
#define O_GC    57116820UL
#define O_GO    57125012UL

// ------------------------------------------------------------------ CSR build
__global__ void k_count(const int* __restrict__ col, int* __restrict__ cnt) {
    int i = blockIdx.x * blockDim.x + threadIdx.x;
    if (i < NE) atomicAdd(&cnt[col[i]], 1);
}

__global__ void k_scan(const int* __restrict__ cnt, int* __restrict__ offs) {
    __shared__ int sm[1024];
    int t = threadIdx.x;
    const int per = (NN + 1023) / 1024;
    int b = t * per, e = min(NN, b + per);
    int s = 0;
    for (int i = b; i < e; i++) s += cnt[i];
    sm[t] = s;
    __syncthreads();
    for (int o = 1; o < 1024; o <<= 1) {
        int v = (t >= o) ? sm[t - o] : 0;
        __syncthreads();
        sm[t] += v;
        __syncthreads();
    }
    int base = (t == 0) ? 0 : sm[t - 1];
    for (int i = b; i < e; i++) { offs[i] = base; base += cnt[i]; }
    if (t == 1023) offs[NN] = sm[1023];
}

__global__ void k_fill(const int* __restrict__ col, int* __restrict__ fill,
                       int* __restrict__ perm, int* __restrict__ ip) {
    int i = blockIdx.x * blockDim.x + threadIdx.x;
    if (i < NE) {
        int p = atomicAdd(&fill[col[i]], 1);
        perm[p] = i;
        ip[i] = p;
    }
}

__global__ void k_rowp(const int* __restrict__ perm, const int* __restrict__ row,
                       int* __restrict__ rowp) {
    int p = blockIdx.x * blockDim.x + threadIdx.x;
    if (p < NE) rowp[p] = row[perm[p]];
}

__global__ void k_permattn(const int* __restrict__ perm, const float* __restrict__ attn,
                           float* __restrict__ attnp) {
    int p = blockIdx.x * blockDim.x + threadIdx.x;
    if (p < NE) attnp[p] = attn[perm[p]];
}

// ------------------------------------------------------------------ BN stats
__global__ void k_colstat(const float* __restrict__ X, int rows, double* __restrict__ sums) {
    int c = threadIdx.x;  // 128
    double s = 0, s2 = 0;
    #pragma unroll 4
    for (int r = blockIdx.x; r < rows; r += gridDim.x) {
        float v = X[(size_t)r * 128 + c];
        s += v; s2 += (double)v * v;
    }
    atomicAdd(&sums[c], s);
    atomicAdd(&sums[128 + c], s2);
}

__global__ void k_bnfin(const double* __restrict__ sums, int rows,
                        float* __restrict__ mu, float* __restrict__ inv) {
    int c = threadIdx.x;
    double m = sums[c] / rows;
    double v = sums[128 + c] / rows - m * m;
    mu[c] = (float)m;
    inv[c] = (float)rsqrt(v + 1e-5);
}

// BN moments of edge_c = attn*e and edge_o = (1-attn)*e in one pass
__global__ void k_edgemom(const float* __restrict__ E4, const float* __restrict__ attn,
                          double* __restrict__ sums) {
    int t = threadIdx.x;  // 128
    double sc = 0, sc2 = 0, so = 0, so2 = 0;
    #pragma unroll 4
    for (int r = blockIdx.x; r < NE; r += gridDim.x) {
        float w = attn[r];
        float v = E4[(size_t)r * 128 + t];
        float tc = w * v, to = (1.f - w) * v;
        sc += tc; sc2 += (double)tc * tc;
        so += to; so2 += (double)to * to;
    }
    atomicAdd(&sums[t], sc);
    atomicAdd(&sums[128 + t], sc2);
    atomicAdd(&sums[256 + t], so);
    atomicAdd(&sums[384 + t], so2);
}

__global__ void k_edgemomfin(const double* __restrict__ sums,
                             float* __restrict__ muc, float* __restrict__ invc,
                             float* __restrict__ muo, float* __restrict__ invo) {
    int c = threadIdx.x;
    double m = sums[c] / NE, v = sums[128 + c] / NE - m * m;
    muc[c] = (float)m; invc[c] = (float)rsqrt(v + 1e-5);
    m = sums[256 + c] / NE; v = sums[384 + c] / NE - m * m;
    muo[c] = (float)m; invo[c] = (float)rsqrt(v + 1e-5);
}

// ------------------------------------------------------------------ per-layer weight prep
__global__ void k_wprep(const float* __restrict__ We, const float* __restrict__ b1,
                        const float* __restrict__ a2, int fe, int need_em,
                        float* __restrict__ A2, float* __restrict__ C2,
                        float* __restrict__ WeM, float* __restrict__ B1M,
                        float* __restrict__ Wperm) {
    int i = blockIdx.x * blockDim.x + threadIdx.x;
    if (i < fe * 3) {
        int f = i / 3, h = i % 3;
        float s = 0;
        for (int d = 0; d < 128; d++) s += We[(size_t)(f * 3 + h) * 128 + d] * a2[h * 128 + d];
        A2[i] = s;
    }
    if (i < 3) {
        float s = 0;
        for (int d = 0; d < 128; d++) s += b1[i * 128 + d] * a2[i * 128 + d];
        C2[i] = s;
    }
    if (i < 128) B1M[i] = (b1[i] + b1[128 + i] + b1[256 + i]) * (1.f / 3.f);
    if (need_em && i < fe * 128) {
        int f = i / 128, d = i % 128;
        WeM[i] = (We[(size_t)(f * 3) * 128 + d] + We[(size_t)(f * 3 + 1) * 128 + d] +
                  We[(size_t)(f * 3 + 2) * 128 + d]) * (1.f / 3.f);
    }
    if (i < 3 * fe * 128) {
        int hi = i / 128, d = i % 128;
        int h = hi / fe, f = hi % fe;
        Wperm[i] = We[(size_t)(f * 3 + h) * 128 + d];
    }
}

// ------------------------------------------------------------------ node scores (warp/node)
__global__ void k_nodescore(const float* __restrict__ H, const float* __restrict__ a,
                            float* __restrict__ ssrc, float* __restrict__ sdst,
                            float* __restrict__ hm) {
    int n = blockIdx.x * (blockDim.x >> 5) + (threadIdx.x >> 5);
    int lane = threadIdx.x & 31;
    if (n >= NN) return;
    const float* hp = H + (size_t)n * 384;
    float s[6] = {0, 0, 0, 0, 0, 0};
    #pragma unroll
    for (int q = 0; q < 4; q++) {
        int f = lane + q * 32;
        float h0 = hp[f], h1 = hp[128 + f], h2 = hp[256 + f];
        hm[(size_t)n * 128 + f] = (h0 + h1 + h2) * (1.f / 3.f);
        s[0] += h0 * a[f];       s[1] += h1 * a[128 + f]; s[2] += h2 * a[256 + f];
        s[3] += h0 * a[384 + f]; s[4] += h1 * a[512 + f]; s[5] += h2 * a[640 + f];
    }
    #pragma unroll
    for (int o = 16; o > 0; o >>= 1) {
        #pragma unroll
        for (int q = 0; q < 6; q++) s[q] += __shfl_xor_sync(0xffffffffu, s[q], o);
    }
    if (lane < 3) {
        ssrc[n * 3 + lane] = s[lane];
        sdst[n * 3 + lane] = s[3 + lane];
    }
}

// ------------------------------------------------------------------ edge logits (warp/edge) -> CSR-ordered
__global__ void k_edgelogit(const float* __restrict__ ef, int fe,
                            const int* __restrict__ row, const int* __restrict__ colv,
                            const int* __restrict__ ip,
                            const float* __restrict__ ssrc, const float* __restrict__ sdst,
                            const float* __restrict__ A2, const float* __restrict__ C2,
                            const float* __restrict__ attn, int oneminus,
                            const float* __restrict__ mu, const float* __restrict__ inv,
                            float* __restrict__ logits, float* __restrict__ eattn, int do_attn) {
    int gw = (blockIdx.x * blockDim.x + threadIdx.x) >> 5;
    int lane = threadIdx.x & 31;
    if (gw >= NE) return;
    float w = 1.f;
    if (attn) { w = attn[gw]; if (oneminus) w = 1.f - w; }
    float p0 = 0, p1 = 0, p2 = 0;
    if (fe == 128) {
        int i = lane * 4;
        float4 v4 = *(const float4*)&ef[(size_t)gw * 128 + i];
        float v[4] = {v4.x, v4.y, v4.z, v4.w};
        #pragma unroll
        for (int q = 0; q < 4; q++) {
            float v1 = v[q];
            if (mu) v1 = (w * v1 - mu[i + q]) * inv[i + q] + 1e-4f;
            p0 += v1 * A2[(i + q) * 3 + 0];
            p1 += v1 * A2[(i + q) * 3 + 1];
            p2 += v1 * A2[(i + q) * 3 + 2];
        }
    } else {
        for (int i = lane; i < fe; i += 32) {
            float v = ef[(size_t)gw * fe + i];
            if (mu) v = (w * v - mu[i]) * inv[i] + 1e-4f;
            p0 += v * A2[i * 3 + 0];
            p1 += v * A2[i * 3 + 1];
            p2 += v * A2[i * 3 + 2];
        }
    }
    #pragma unroll
    for (int o = 16; o > 0; o >>= 1) {
        p0 += __shfl_down_sync(0xffffffffu, p0, o);
        p1 += __shfl_down_sync(0xffffffffu, p1, o);
        p2 += __shfl_down_sync(0xffffffffu, p2, o);
    }
    if (lane == 0) {
        int r = row[gw], c = colv[gw];
        float l0 = ssrc[r * 3 + 0] + sdst[c * 3 + 0] + p0 + C2[0];
        float l1 = ssrc[r * 3 + 1] + sdst[c * 3 + 1] + p1 + C2[1];
        float l2 = ssrc[r * 3 + 2] + sdst[c * 3 + 2] + p2 + C2[2];
        l0 = l0 > 0.f ? l0 : 0.2f * l0;
        l1 = l1 > 0.f ? l1 : 0.2f * l1;
        l2 = l2 > 0.f ? l2 : 0.2f * l2;
        int pos = ip[gw];
        logits[pos * 3 + 0] = l0;
        logits[pos * 3 + 1] = l1;
        logits[pos * 3 + 2] = l2;
        if (do_attn) {
            float m = (l0 + l1 + l2) * (1.f / 3.f);
            eattn[gw] = 1.f / (1.f + expf(-m));
        }
    }
}

// ------------------------------------------------------------------ per-node softmax + aggregation
// L is CSR-ordered logits; overwritten with exp(l - max) in pass 2.
__global__ void k_nodeagg(const int* __restrict__ offs, const int* __restrict__ perm,
                          const int* __restrict__ rowp,
                          float* __restrict__ L, const float* __restrict__ H,
                          const float* __restrict__ ef, int fe,
                          const float* __restrict__ attnp, int oneminus,
                          const float* __restrict__ mu, const float* __restrict__ inv,
                          float* __restrict__ agghs, float* __restrict__ aggE,
                          float* __restrict__ asum) {
    __shared__ float red[3][128];
    __shared__ float sval[6];
    int n = blockIdx.x, t = threadIdx.x;
    int s = offs[n], e = offs[n + 1];

    // pass 1: per-head max (contiguous)
    float mx0 = -1e30f, mx1 = -1e30f, mx2 = -1e30f;
    for (int j = s + t; j < e; j += 128) {
        mx0 = fmaxf(mx0, L[j * 3 + 0]);
        mx1 = fmaxf(mx1, L[j * 3 + 1]);
        mx2 = fmaxf(mx2, L[j * 3 + 2]);
    }
    red[0][t] = mx0; red[1][t] = mx1; red[2][t] = mx2;
    __syncthreads();
    for (int o = 64; o > 0; o >>= 1) {
        if (t < o) {
            red[0][t] = fmaxf(red[0][t], red[0][t + o]);
            red[1][t] = fmaxf(red[1][t], red[1][t + o]);
            red[2][t] = fmaxf(red[2][t], red[2][t + o]);
        }
        __syncthreads();
    }
    if (t < 3) sval[t] = red[t][0];
    __syncthreads();
    float m0 = sval[0], m1 = sval[1], m2 = sval[2];

    // pass 2: exp, writeback, sum
    float sm0 = 0, sm1 = 0, sm2 = 0;
    for (int j = s + t; j < e; j += 128) {
        float w0 = expf(L[j * 3 + 0] - m0);
        float w1 = expf(L[j * 3 + 1] - m1);
        float w2 = expf(L[j * 3 + 2] - m2);
        L[j * 3 + 0] = w0; L[j * 3 + 1] = w1; L[j * 3 + 2] = w2;
        sm0 += w0; sm1 += w1; sm2 += w2;
    }
    red[0][t] = sm0; red[1][t] = sm1; red[2][t] = sm2;
    __syncthreads();
    for (int o = 64; o > 0; o >>= 1) {
        if (t < o) {
            red[0][t] += red[0][t + o];
            red[1][t] += red[1][t + o];
            red[2][t] += red[2][t + o];
        }
        __syncthreads();
    }
    if (t < 3) sval[t] = 1.f / (red[t][0] + 1e-16f);
    if (t >= 3 && t < 6) sval[t] = red[t - 3][0];
    __syncthreads();
    float i0 = sval[0], i1 = sval[1], i2 = sval[2];
    if (t == 0) {
        asum[n * 3 + 0] = sval[3] * i0;
        asum[n * 3 + 1] = sval[4] * i1;
        asum[n * 3 + 2] = sval[5] * i2;
    }

    // pass 3: 4-way pipelined aggregation
    float a_hs = 0, aE0 = 0, aE1 = 0, aE2 = 0;
    for (int j0 = s; j0 < e; j0 += 4) {
        int cnt = e - j0; if (cnt > 4) cnt = 4;
        int r[4], id[4];
        float w0[4], w1[4], w2[4], ww[4];
        #pragma unroll
        for (int q = 0; q < 4; q++) {
            if (q < cnt) {
                r[q] = rowp[j0 + q];
                w0[q] = L[(j0 + q) * 3 + 0] * i0;
                w1[q] = L[(j0 + q) * 3 + 1] * i1;
                w2[q] = L[(j0 + q) * 3 + 2] * i2;
                id[q] = perm[j0 + q];
                if (mu) { ww[q] = attnp[j0 + q]; if (oneminus) ww[q] = 1.f - ww[q]; }
            }
        }
        #pragma unroll
        for (int q = 0; q < 4; q++) {
            if (q < cnt) {
                const float* hp = &H[(size_t)r[q] * 384];
                a_hs += w0[q] * hp[t] + w1[q] * hp[128 + t] + w2[q] * hp[256 + t];
                if (t < fe) {
                    float v = ef[(size_t)id[q] * fe + t];
                    if (mu) v = (ww[q] * v - mu[t]) * inv[t] + 1e-4f;
                    aE0 += w0[q] * v; aE1 += w1[q] * v; aE2 += w2[q] * v;
                }
            }
        }
    }
    agghs[(size_t)n * 128 + t] = a_hs;
    if (t < fe) {
        aggE[(size_t)n * 3 * fe + 0 * fe + t] = aE0;
        aggE[(size_t)n * 3 * fe + 1 * fe + t] = aE1;
        aggE[(size_t)n * 3 * fe + 2 * fe + t] = aE2;
    }
}

// ------------------------------------------------------------------ SGEMM 128x128x16, 8x8 microtile
// mode 0: C = A'@B + bias(p0)[n]        (A' = optional BN of A via bnm/bni)
// mode 1: C = relu((A@B + agghs(p0)[m,n] + sum_h asum(p1)[m,h]*b1(p2)[h,n]) / 3)   (N==128)
// mode 2: C = relu(A@B + b1m(p0)[n] + hm(p1)[row[m],n] + hm(p1)[col[m],n])         (N==128)
__global__ void __launch_bounds__(256, 2)
k_gemm(const float* __restrict__ A, const float* __restrict__ B,
       float* __restrict__ C, int M, int N, int K, int mode,
       const float* __restrict__ p0, const float* __restrict__ p1,
       const float* __restrict__ p2,
       const int* __restrict__ ridx, const int* __restrict__ cidx,
       const float* __restrict__ bnm, const float* __restrict__ bni) {
    __shared__ float As[16][128];
    __shared__ float Bs[16][128];
    int bm = blockIdx.y * 128, bn = blockIdx.x * 128;
    int tid = threadIdx.x;
    int tx = tid & 15, ty = tid >> 4;
    float acc[8][8] = {};

    for (int k0 = 0; k0 < K; k0 += 16) {
        #pragma unroll
        for (int rep = 0; rep < 2; rep++) {
            int idx = tid + rep * 256;
            int r = idx >> 2, c4 = (idx & 3) * 4;
            float4 av = make_float4(0.f, 0.f, 0.f, 0.f);
            int arow = bm + r;
            if (arow < M) {
                av = *(const float4*)&A[(size_t)arow * K + k0 + c4];
                if (bnm) {
                    int kk = k0 + c4;
                    av.x = (av.x - bnm[kk + 0]) * bni[kk + 0] + 1e-4f;
                    av.y = (av.y - bnm[kk + 1]) * bni[kk + 1] + 1e-4f;
                    av.z = (av.z - bnm[kk + 2]) * bni[kk + 2] + 1e-4f;
                    av.w = (av.w - bnm[kk + 3]) * bni[kk + 3] + 1e-4f;
                }
            }
            As[c4 + 0][r] = av.x; As[c4 + 1][r] = av.y;
            As[c4 + 2][r] = av.z; As[c4 + 3][r] = av.w;
            int br = idx >> 5, bc4 = (idx & 31) * 4;
            *(float4*)&Bs[br][bc4] = *(const float4*)&B[(size_t)(k0 + br) * N + bn + bc4];
        }
        __syncthreads();
        #pragma unroll
        for (int k = 0; k < 16; k++) {
            float a[8], b[8];
            *(float4*)&a[0] = *(const float4*)&As[k][ty * 4];
            *(float4*)&a[4] = *(const float4*)&As[k][64 + ty * 4];
            *(float4*)&b[0] = *(const float4*)&Bs[k][tx * 4];
            *(float4*)&b[4] = *(const float4*)&Bs[k][64 + tx * 4];
            #pragma unroll
            for (int i = 0; i < 8; i++)
                #pragma unroll
                for (int j = 0; j < 8; j++) acc[i][j] += a[i] * b[j];
        }
        __syncthreads();
    }

    #pragma unroll
    for (int i = 0; i < 8; i++) {
        int m = bm + ((i < 4) ? (ty * 4 + i) : (64 + ty * 4 + i - 4));
        if (m >= M) continue;
        int r = 0, c = 0;
        if (mode == 2) { r = ridx[m]; c = cidx[m]; }
        #pragma unroll
        for (int jg = 0; jg < 2; jg++) {
            int nb = bn + (jg ? (64 + tx * 4) : (tx * 4));
            float4 o;
            float* ov = &o.x;
            #pragma unroll
            for (int j = 0; j < 4; j++) {
                int n = nb + j;
                float v = acc[i][jg * 4 + j];
                if (mode == 0) {
                    v += p0[n];
                } else if (mode == 1) {
                    v += p0[(size_t)m * 128 + n];
                    v += p1[m * 3 + 0] * p2[n] + p1[m * 3 + 1] * p2[128 + n] +
                         p1[m * 3 + 2] * p2[256 + n];
                    v *= (1.f / 3.f);
                    v = fmaxf(v, 0.f);
                } else {
                    v += p0[n];
                    v += p1[(size_t)r * 128 + n] + p1[(size_t)c * 128 + n];
                    v = fmaxf(v, 0.f);
                }
                ov[j] = v;
            }
            *(float4*)&C[(size_t)m * N + nb] = o;
        }
    }
}

// ------------------------------------------------------------------ node attention split
__global__ void k_natt(const float* __restrict__ x, const float* __restrict__ W,
                       const float* __restrict__ b, float* __restrict__ xc,
                       float* __restrict__ xo) {
    int n = blockIdx.x * (blockDim.x >> 5) + (threadIdx.x >> 5);
    int lane = threadIdx.x & 31;
    if (n >= NN) return;
    float d0 = 0, d1 = 0;
    for (int i = lane; i < 128; i += 32) {
        float v = x[(size_t)n * 128 + i];
        d0 += v * W[i * 2 + 0];
        d1 += v * W[i * 2 + 1];
    }
    #pragma unroll
    for (int o = 16; o > 0; o >>= 1) {
        d0 += __shfl_xor_sync(0xffffffffu, d0, o);
        d1 += __shfl_xor_sync(0xffffffffu, d1, o);
    }
    d0 += b[0]; d1 += b[1];
    float mx = fmaxf(d0, d1);
    float e0 = expf(d0 - mx), e1 = expf(d1 - mx);
    float inv = 1.f / (e0 + e1);
    float n0 = e0 * inv, n1 = e1 * inv;
    for (int i = lane; i < 128; i += 32) {
        float v = x[(size_t)n * 128 + i];
        xc[(size_t)n * 128 + i] = n0 * v;
        xo[(size_t)n * 128 + i] = n1 * v;
    }
}

// ------------------------------------------------------------------ graph pooling
__global__ void k_segsum(const float* __restrict__ x, const int* __restrict__ batch,
                         float* __restrict__ g) {
    int i = blockIdx.x * blockDim.x + threadIdx.x;
    if (i < NN * 128) {
        int n = i >> 7;
        atomicAdd(&g[(size_t)batch[n] * 128 + (i & 127)], x[i]);
    }
}

// ------------------------------------------------------------------ readout (3 blocks)
__global__ void k_readout(const float* __restrict__ gc, const float* __restrict__ go,
                          const float* __restrict__ W1s, const float* __restrict__ b1s,
                          const float* __restrict__ W2s, const float* __restrict__ b2s,
                          float* __restrict__ out) {
    int which = blockIdx.x, t = threadIdx.x;
    __shared__ float M[64][129];
    __shared__ float Z[64][12];
    const float* W1 = W1s + which * 16384;
    const float* B1 = b1s + which * 128;
    const float* W2 = W2s + which * 1280;
    const float* B2 = b2s + which * 10;

    double s = 0, s2 = 0;
    for (int r = 0; r < 64; r++) {
        float v = (which == 0) ? gc[r * 128 + t]
                : (which == 1) ? go[r * 128 + t]
                               : gc[r * 128 + t] + go[r * 128 + t];
        s += v; s2 += (double)v * v;
    }
    double mud = s / 64.0;
    float mu = (float)mud;
    float iv = (float)rsqrt(s2 / 64.0 - mud * mud + 1e-5);
    for (int r = 0; r < 64; r++) {
        float v = (which == 0) ? gc[r * 128 + t]
                : (which == 1) ? go[r * 128 + t]
                               : gc[r * 128 + t] + go[r * 128 + t];
        M[r][t] = (v - mu) * iv + 1e-4f;
    }
    __syncthreads();

    float y[64];
    for (int r = 0; r < 64; r++) {
        float acc = B1[t];
        for (int k = 0; k < 128; k++) acc += M[r][k] * W1[k * 128 + t];
        y[r] = fmaxf(acc, 0.f);
    }
    s = 0; s2 = 0;
    for (int r = 0; r < 64; r++) { s += y[r]; s2 += (double)y[r] * y[r]; }
    mud = s / 64.0;
    mu = (float)mud;
    iv = (float)rsqrt(s2 / 64.0 - mud * mud + 1e-5);
    __syncthreads();
    for (int r = 0; r < 64; r++) M[r][t] = (y[r] - mu) * iv + 1e-4f;
    __syncthreads();

    if (t < 10) {
        for (int r = 0; r < 64; r++) {
            float acc = B2[t];
            for (int k = 0; k < 128; k++) acc += M[r][k] * W2[k * 10 + t];
            Z[r][t] = acc;
        }
    }
    __syncthreads();
    if (t < 64) {
        float mx = -1e30f;
        for (int c = 0; c < 10; c++) mx = fmaxf(mx, Z[t][c]);
        float sm = 0;
        for (int c = 0; c < 10; c++) sm += expf(Z[t][c] - mx);
        float l = mx + logf(sm);
        for (int c = 0; c < 10; c++) out[which * 640 + t * 10 + c] = Z[t][c] - l;
    }
}

// ------------------------------------------------------------------ host-side layer driver
static void run_layer(float* F, double* DS, int* I,
                      const float* xin, const float* ef, int fe,
                      const float* Wn, const float* We, const float* bb, const float* aa,
                      const int* row, const int* col,
                      float* xout, float* eout,
                      const float* attn, const float* attnp, int oneminus,
                      const float* mu, const float* inv, float* eattn) {
    int* OFFS = I + 10000;
    int* PERM = I + 30001;
    int* IP   = I + 190001;
    int* ROWP = I + 350001;

    cudaMemsetAsync(DS, 0, 256 * sizeof(double), 0);
    k_colstat<<<640, 128>>>(xin, NN, DS);
    k_bnfin<<<1, 128>>>(DS, NN, F + O_MU, F + O_INV);
    k_gemm<<<dim3(3, (NN + 127) / 128), 256>>>(xin, Wn, F + O_H, NN, 384, 128, 0,
                                               bb, nullptr, nullptr, nullptr, nullptr,
                                               F + O_MU, F + O_INV);
    k_nodescore<<<(NN + 7) / 8, 256>>>(F + O_H, aa, F + O_SSRC, F + O_SDST, F + O_HM);
    k_wprep<<<(3 * fe * 128 + 255) / 256, 256>>>(We, bb + 384, aa + 768, fe,
                                                 eout ? 1 : 0, F + O_A2, F + O_C2,
                                                 F + O_WEM, F + O_B1M, F + O_WPERM);
    k_edgelogit<<<NE / 8, 256>>>(ef, fe, row, col, IP, F + O_SSRC, F + O_SDST,
                                 F + O_A2, F + O_C2, attn, oneminus, mu, inv,
                                 F + O_LOG, eattn, eattn ? 1 : 0);
    k_nodeagg<<<NN, 128>>>(OFFS, PERM, ROWP, F + O_LOG, F + O_H, ef, fe,
                           attnp, oneminus, mu, inv,
                           F + O_AGGHS, F + O_AGGE, F + O_ASUM);
    k_gemm<<<dim3(1, (NN + 127) / 128), 256>>>(F + O_AGGE, F + O_WPERM, xout,
                                               NN, 128, 3 * fe, 1,
                                               F + O_AGGHS, F + O_ASUM, bb + 384,
                                               nullptr, nullptr, nullptr, nullptr);
    if (eout)
        k_gemm<<<dim3(1, (NE + 127) / 128), 256>>>(ef, F + O_WEM, eout, NE, 128, fe, 2,
                                                   F + O_B1M, F + O_HM, nullptr, row, col,
                                                   nullptr, nullptr);
}

extern "C" void kernel_launch(void* const* d_in, const int* in_sizes, int n_in,
                              void* d_out, int out_size) {
    float* F; cudaGetSymbolAddress((void**)&F, g_f);
    double* DS; cudaGetSymbolAddress((void**)&DS, g_d);
    int* I; cudaGetSymbolAddress((void**)&I, g_i);

    const float* x     = (const float*)d_in[0];
    const float* eattr = (const float*)d_in[1];
    const float* Wn0   = (const float*)d_in[2];
    const float* We0   = (const float*)d_in[3];
    const float* b0    = (const float*)d_in[4];
    const float* a0    = (const float*)d_in[5];
    const float* Wn    = (const float*)d_in[6];
    const float* We    = (const float*)d_in[7];
    const float* bb    = (const float*)d_in[8];
    const float* aa    = (const float*)d_in[9];
    const float* nattW = (const float*)d_in[10];
    const float* nattB = (const float*)d_in[11];
    const float* fcW1  = (const float*)d_in[12];
    const float* fcb1  = (const float*)d_in[13];
    const float* fcW2  = (const float*)d_in[14];
    const float* fcb2  = (const float*)d_in[15];
    const int* eidx    = (const int*)d_in[16];
    const int* batch   = (const int*)d_in[17];
    const int* row = eidx;
    const int* col = eidx + NE;

    int* CNT  = I;
    int* OFFS = I + 10000;
    int* FILL = I + 20001;
    int* PERM = I + 30001;
    int* IP   = I + 190001;
    int* ROWP = I + 350001;

    // CSR by destination (reused by all 6 layers)
    cudaMemsetAsync(CNT, 0, NN * sizeof(int), 0);
    k_count<<<(NE + 255) / 256, 256>>>(col, CNT);
    k_scan<<<1, 1024>>>(CNT, OFFS);
    cudaMemcpyAsync(FILL, OFFS, NN * sizeof(int), cudaMemcpyDeviceToDevice, 0);
    k_fill<<<(NE + 255) / 256, 256>>>(col, FILL, PERM, IP);
    k_rowp<<<(NE + 255) / 256, 256>>>(PERM, row, ROWP);

    // layer 0: fe=16
    run_layer(F, DS, I, x, eattr, 16, Wn0, We0, b0, a0, row, col,
              F + O_X1, F + O_EA, nullptr, nullptr, 0, nullptr, nullptr, nullptr);
    // layers 1..3 (weights idx 0..2)
    run_layer(F, DS, I, F + O_X1, F + O_EA, 128, Wn, We, bb, aa, row, col,
              F + O_X1, F + O_EB, nullptr, nullptr, 0, nullptr, nullptr, nullptr);
    run_layer(F, DS, I, F + O_X1, F + O_EB, 128, Wn + 49152, We + 49152, bb + 768,
              aa + 1152, row, col, F + O_X1, F + O_EA, nullptr, nullptr, 0,
              nullptr, nullptr, nullptr);
    run_layer(F, DS, I, F + O_X1, F + O_EA, 128, Wn + 2 * 49152, We + 2 * 49152,
              bb + 2 * 768, aa + 2 * 1152, row, col,
              F + O_X1, F + O_EB, nullptr, nullptr, 0, nullptr, nullptr, F + O_EATTN);

    // node attention split
    k_natt<<<(NN + 7) / 8, 256>>>(F + O_X1, nattW, nattB, F + O_XC, F + O_XO);

    // CSR-ordered copy of edge attention for branch-layer aggregation
    k_permattn<<<(NE + 255) / 256, 256>>>(PERM, F + O_EATTN, F + O_ATTNP);

    // edge_c / edge_o BN moments (folded transform, no materialization)
    cudaMemsetAsync(DS, 0, 512 * sizeof(double), 0);
    k_edgemom<<<1024, 128>>>(F + O_EB, F + O_EATTN, DS);
    k_edgemomfin<<<1, 128>>>(DS, F + O_MUC, F + O_INVC, F + O_MUO, F + O_INVO);

    // causal / non-causal branches (weights idx 3 / 4), no e_out
    run_layer(F, DS, I, F + O_XC, F + O_EB, 128, Wn + 3 * 49152, We + 3 * 49152,
              bb + 3 * 768, aa + 3 * 1152, row, col,
              F + O_XC, nullptr, F + O_EATTN, F + O_ATTNP, 0, F + O_MUC, F + O_INVC, nullptr);
    run_layer(F, DS, I, F + O_XO, F + O_EB, 128, Wn + 4 * 49152, We + 4 * 49152,
              bb + 4 * 768, aa + 4 * 1152, row, col,
              F + O_XO, nullptr, F + O_EATTN, F + O_ATTNP, 1, F + O_MUO, F + O_INVO, nullptr);

    // graph pooling
    cudaMemsetAsync(F + O_GC, 0, 2 * NG * 128 * sizeof(float), 0);
    k_segsum<<<(NN * 128 + 255) / 256, 256>>>(F + O_XC, batch, F + O_GC);
    k_segsum<<<(NN * 128 + 255) / 256, 256>>>(F + O_XO, batch, F + O_GO);

    // readouts
    k_readout<<<3, 128>>>(F + O_GC, F + O_GO, fcW1, fcb1, fcW2, fcb2, (float*)d_out);
}